// round 1
// baseline (speedup 1.0000x reference)
#include <cuda_runtime.h>
#include <cuda_bf16.h>

// Problem constants
// x:      (256, 64, 25, 3)  float32   -> d_in[0], 1228800 elems
// W_conv: (3, 192)          float32   -> d_in[1], 576 elems
// W_a:    (128, 1)          float32   -> d_in[2], 128 elems
// out:    (256, 3, 25, 25)  float32   -> 480000 elems
//
// Reduction: mean over T commutes with all linear ops, so
//   xbar[n,v,i] = mean_t x[n,t,v,i]
//   u{1,2}[i,k] = sum_c W_conv[i, c*3+k] * W_a[{0,64}+c]
//   s{1,2}[n,v,k] = sum_i xbar[n,v,i] * u{1,2}[i,k]
//   out row (n,kk,p): q in 0..24, L = kk*625+p*25+q,
//     a=L/75, b=(L%75)/3, k=L%3, e = s1[b,k]+s2[a,k], leaky(0.2), softmax over q.

#define TPB 256

__global__ __launch_bounds__(TPB, 2)
void gat_adj_kernel(const float* __restrict__ x,
                    const float* __restrict__ Wc,
                    const float* __restrict__ Wa,
                    float* __restrict__ out)
{
    __shared__ float xsh[4800];       // x tile (64*75); reused as E buffer (1875)
    __shared__ float part[3][75];
    __shared__ float xbar[75];
    __shared__ float u[2][3][3];      // u[0]=u1, u[1]=u2
    __shared__ float s1sh[75], s2sh[75];

    const int n   = blockIdx.x;
    const int tid = threadIdx.x;

    // ---- Phase 1: coalesced float4 load of this sample's x tile ----
    {
        const float4* xg  = reinterpret_cast<const float4*>(x + (size_t)n * 4800);
        float4*       xs4 = reinterpret_cast<float4*>(xsh);
        #pragma unroll
        for (int i = tid; i < 1200; i += TPB) xs4[i] = xg[i];
    }

    // ---- Concurrent: u matrices (18 threads, 64 MACs each) ----
    if (tid < 18) {
        const int which = tid / 9;          // 0 -> wa1, 1 -> wa2
        const int rem   = tid % 9;
        const int i     = rem / 3;
        const int k     = rem % 3;
        float acc = 0.f;
        #pragma unroll 8
        for (int c = 0; c < 64; c++)
            acc += Wc[i * 192 + c * 3 + k] * Wa[which * 64 + c];
        u[which][i][k] = acc;
    }
    __syncthreads();

    // ---- Phase 2: column sums over T (3 groups x 75 cols) ----
    {
        const int g = tid / 75;
        const int j = tid % 75;
        if (g < 3) {
            const int t0 = (g == 0) ? 0  : (g == 1) ? 22 : 43;
            const int t1 = (g == 0) ? 22 : (g == 1) ? 43 : 64;
            float acc = 0.f;
            for (int t = t0; t < t1; t++) acc += xsh[t * 75 + j];
            part[g][j] = acc;
        }
    }
    __syncthreads();

    if (tid < 75)
        xbar[tid] = (part[0][tid] + part[1][tid] + part[2][tid]) * (1.0f / 64.0f);
    __syncthreads();

    // ---- Phase 3: s1/s2 via 3x3 matmul ----
    if (tid < 75) {
        const int v = tid / 3;
        const int k = tid % 3;
        const float a0 = xbar[v * 3 + 0];
        const float a1 = xbar[v * 3 + 1];
        const float a2 = xbar[v * 3 + 2];
        s1sh[tid] = a0 * u[0][0][k] + a1 * u[0][1][k] + a2 * u[0][2][k];
        s2sh[tid] = a0 * u[1][0][k] + a1 * u[1][1][k] + a2 * u[1][2][k];
    }
    __syncthreads();

    // ---- Phase 4: leaky + softmax; one thread per output row (75 rows x 25) ----
    // Reuse xsh as the E/result buffer (all reads of the x tile are done).
    if (tid < 75) {
        float vals[25];
        float mx = -1e30f;
        #pragma unroll
        for (int q = 0; q < 25; q++) {
            const int L = tid * 25 + q;    // flat index within sample
            const int a = L / 75;
            const int r = L % 75;
            const int b = r / 3;
            const int k = r % 3;
            float e = s1sh[b * 3 + k] + s2sh[a * 3 + k];
            e = (e >= 0.f) ? e : 0.2f * e;
            vals[q] = e;
            mx = fmaxf(mx, e);
        }
        float sum = 0.f;
        #pragma unroll
        for (int q = 0; q < 25; q++) {
            vals[q] = __expf(vals[q] - mx);
            sum += vals[q];
        }
        const float inv = 1.0f / sum;
        #pragma unroll
        for (int q = 0; q < 25; q++)
            xsh[tid * 25 + q] = vals[q] * inv;  // stride 25 vs 32 banks: conflict-free
    }
    __syncthreads();

    // ---- Phase 5: coalesced store ----
    {
        float* og = out + (size_t)n * 1875;
        for (int m = tid; m < 1875; m += TPB) og[m] = xsh[m];
    }
}

extern "C" void kernel_launch(void* const* d_in, const int* in_sizes, int n_in,
                              void* d_out, int out_size)
{
    const float* x  = (const float*)d_in[0];
    const float* Wc = (const float*)d_in[1];
    const float* Wa = (const float*)d_in[2];
    float* out = (float*)d_out;
    gat_adj_kernel<<<256, TPB>>>(x, Wc, Wa, out);
}

// round 3
// speedup vs baseline: 1.0107x; 1.0107x over previous
#include <cuda_runtime.h>
#include <cuda_bf16.h>

// x:      (256, 64, 25, 3)  float32 -> d_in[0]
// W_conv: (3, 192)          float32 -> d_in[1]
// W_a:    (128, 1)          float32 -> d_in[2]
// out:    (256, 3, 25, 25)  float32
//
// Verified math (R1):
//   xbar[n,j] = sum_t x[n,t,j], j = v*3+i (mean's 1/64 folded into u)
//   u{1,2}[i,k] = (1/64) sum_c W_conv[i,c*3+k]*W_a[{0,64}+c]
//   s{1,2}[v,k] = sum_i xbar[v*3+i]*u{1,2}[i,k]
//   out row `row` (0..74), col q: a=row/3 ... L=row*25+q, a=L/75, r=L%75=(row%3)*25+q
//   e = s1[r] + s2[(row/3)*3 + (r%3)];  E = leaky(e, 0.2);  softmax over q.
// LeakyReLU is NONLINEAR -> no exp factorization (R2 bug). Instead:
//   leaky(e) = max(e, 0.2e); store packed (s*log2e, 0.2*s*log2e) so one f32x2 add
//   yields both candidates, then FMNMX + bare ex2.approx.

#define TPB 320

__device__ __forceinline__ unsigned long long add2(unsigned long long a, unsigned long long b) {
    unsigned long long r;
    asm("add.rn.f32x2 %0, %1, %2;" : "=l"(r) : "l"(a), "l"(b));
    return r;
}
__device__ __forceinline__ unsigned long long pack2(float lo, float hi) {
    unsigned long long r;
    asm("mov.b64 %0, {%1, %2};" : "=l"(r) : "f"(lo), "f"(hi));
    return r;
}
__device__ __forceinline__ void unpack2(unsigned long long v, float &lo, float &hi) {
    asm("mov.b64 {%0, %1}, %2;" : "=f"(lo), "=f"(hi) : "l"(v));
}
__device__ __forceinline__ float ex2a(float x) {
    float r; asm("ex2.approx.f32 %0, %1;" : "=f"(r) : "f"(x)); return r;
}

__global__ __launch_bounds__(TPB)
void gat_adj_kernel(const float* __restrict__ x,
                    const float* __restrict__ Wc,
                    const float* __restrict__ Wa,
                    float* __restrict__ out)
{
    __shared__ __align__(16) float buf[1200];          // 16 partial slots x 75 cols
    __shared__ float xbar[75];
    __shared__ float uu[18];                           // [which*9 + i*3 + k], /64 folded
    __shared__ unsigned long long sp1[75], sp2[75];    // packed (s*L2E, 0.2*s*L2E)

    const int n   = blockIdx.x;
    const int tid = threadIdx.x;

    // ---- Phase 1: ldg.128 + in-register partial T-reduction (f32x2 adds) ----
    // float4 #r+300k: its floats' columns (4r+m)%75 are k-invariant (1200%75==0).
    if (tid < 300) {
        const ulonglong2* xg = reinterpret_cast<const ulonglong2*>(x + (size_t)n * 4800);
        ulonglong2 a = xg[tid];
        ulonglong2 b = xg[tid + 300];
        ulonglong2 c = xg[tid + 600];
        ulonglong2 d = xg[tid + 900];
        ulonglong2 s;
        s.x = add2(add2(a.x, b.x), add2(c.x, d.x));
        s.y = add2(add2(a.y, b.y), add2(c.y, d.y));
        reinterpret_cast<ulonglong2*>(buf)[tid] = s;
    } else if (tid < 318) {
        const int idx = tid - 300, which = idx / 9, rem = idx % 9;
        const int i = rem / 3, k = rem % 3;
        float acc = 0.f;
        #pragma unroll 8
        for (int cc = 0; cc < 64; cc++)
            acc += Wc[i * 192 + cc * 3 + k] * Wa[which * 64 + cc];
        uu[idx] = acc * (1.0f / 64.0f);
    }
    __syncthreads();

    // ---- Phase 2: fold 16 partial slots per column ----
    if (tid < 75) {
        float acc = 0.f;
        #pragma unroll
        for (int i = 0; i < 16; i++) acc += buf[i * 75 + tid];
        xbar[tid] = acc;
    }
    __syncthreads();

    // ---- Phase 3: s1/s2 (3x3), pre-scale by log2(e), pack with 0.2x copies ----
    if (tid < 75) {
        const int k  = tid % 3;
        const int v3 = tid - k;
        const float a0 = xbar[v3], a1 = xbar[v3 + 1], a2 = xbar[v3 + 2];
        const float L2E = 1.4426950408889634f;
        const float s1 = (a0 * uu[k]     + a1 * uu[3 + k]  + a2 * uu[6 + k])  * L2E;
        const float s2 = (a0 * uu[9 + k] + a1 * uu[12 + k] + a2 * uu[15 + k]) * L2E;
        sp1[tid] = pack2(s1, 0.2f * s1);
        sp2[tid] = pack2(s2, 0.2f * s2);
    }
    __syncthreads();

    // ---- Phase 4: softmax, 4 threads per row, all 320 threads active ----
    {
        int row = tid >> 2;
        if (row > 74) row = 74;                 // lanes 300..319 do safe duplicate work
        const int part = tid & 3;
        const int d  = row % 3;
        const int a3 = row - d;                 // (row/3)*3
        const int r0 = d * 25;

        const unsigned long long c0 = sp2[a3];
        const unsigned long long c1 = sp2[a3 + 1];
        const unsigned long long c2 = sp2[a3 + 2];

        const int qs  = (part == 0) ? 0 : part * 6 + 1;   // 0,7,13,19
        const int cnt = (part == 0) ? 7 : 6;

        // rotate-register trick: start rotation at kk0=(d+qs)%3, then rotate per q
        const int kk0 = (d + qs) % 3;
        unsigned long long ra = (kk0 == 0) ? c0 : ((kk0 == 1) ? c1 : c2);
        unsigned long long rb = (kk0 == 0) ? c1 : ((kk0 == 1) ? c2 : c0);
        unsigned long long rc = (kk0 == 0) ? c2 : ((kk0 == 1) ? c0 : c1);

        float vals[7];
        float sum = 0.f;
        #pragma unroll
        for (int j = 0; j < 7; j++) {
            if (j < cnt) {
                unsigned long long ef = add2(sp1[r0 + qs + j], ra);
                float e, f;
                unpack2(ef, e, f);
                const float vl = ex2a(fmaxf(e, f));   // exp2 of log2e-scaled leaky
                vals[j] = vl;
                sum += vl;
                // rotate (pure renaming after unroll)
                unsigned long long t = ra; ra = rb; rb = rc; rc = t;
            }
        }
        sum += __shfl_xor_sync(0xffffffffu, sum, 1);
        sum += __shfl_xor_sync(0xffffffffu, sum, 2);
        const float inv = __fdividef(1.0f, sum);

        if ((tid >> 2) < 75) {
            float* og = out + (size_t)n * 1875 + row * 25 + qs;
            #pragma unroll
            for (int j = 0; j < 7; j++)
                if (j < cnt) og[j] = vals[j] * inv;
        }
    }
}

extern "C" void kernel_launch(void* const* d_in, const int* in_sizes, int n_in,
                              void* d_out, int out_size)
{
    const float* x  = (const float*)d_in[0];
    const float* Wc = (const float*)d_in[1];
    const float* Wa = (const float*)d_in[2];
    float* out = (float*)d_out;
    gat_adj_kernel<<<256, TPB>>>(x, Wc, Wa, out);
}